// round 17
// baseline (speedup 1.0000x reference)
#include <cuda_runtime.h>
#include <cuda_fp16.h>
#include <cstdint>

// B=1024, T=512, I=H=256, 3H=768
#define Bsz 1024
#define Tsz 512
#define MGN 16     // batch groups (64 rows each) = clusters
#define UGN 8      // unit groups (32 units -> 96 gate rows, gate-blocked r|z|n) = cluster size

// ---------------- device scratch (static) ----------------
// xi (no bias), fp16, T-MAJOR: index = (t*Bsz + b)*768 + col, col = ug*96+gate*32+u
__device__ __align__(16) __half g_xi[(size_t)Bsz * Tsz * 768];
__device__ __align__(16) __half g_W[2][UGN][2][96 * 256];    // [mat][ug][hi/lo][j*256+k]
__device__ float g_bias[1024];  // [0]=br(ih+hh) [256]=bz(ih+hh) [512]=b_ih_n [768]=b_hh_n

// ---------------- SMEM layouts (bytes) ----------------
#define AROW  528                 // 264 halves per row (pad keeps ldsm phases conflict-free)
// gru_rec: A0(64x528=33792) | A1(33792) | W_hi (50688)  — A double buffered for DSMEM exchange
#define OFF_A1  33792
#define OFF_W   67584
#define WPASS   50688
#define SMEM_REC (OFF_W + WPASS)
// xproj: A(128x528=67584) | W_hi (50688)
#define OFF_WX  67584
#define SMEM_XP (OFF_WX + WPASS)

// ---------------- helpers ----------------
__device__ __forceinline__ uint32_t smem_u32(const void* p) {
    uint32_t a;
    asm("{ .reg .u64 t; cvta.to.shared.u64 t, %1; cvt.u32.u64 %0, t; }" : "=r"(a) : "l"(p));
    return a;
}
__device__ __forceinline__ void ldsm4(uint32_t* r, uint32_t a) {
    asm volatile("ldmatrix.sync.aligned.m8n8.x4.shared.b16 {%0,%1,%2,%3}, [%4];"
                 : "=r"(r[0]), "=r"(r[1]), "=r"(r[2]), "=r"(r[3]) : "r"(a));
}
__device__ __forceinline__ void ldsm2(uint32_t* r, uint32_t a) {
    asm volatile("ldmatrix.sync.aligned.m8n8.x2.shared.b16 {%0,%1}, [%2];"
                 : "=r"(r[0]), "=r"(r[1]) : "r"(a));
}
__device__ __forceinline__ void mma16816(float* d, const uint32_t* a, const uint32_t* b) {
    asm volatile("mma.sync.aligned.m16n8k16.row.col.f32.f16.f16.f32 "
                 "{%0,%1,%2,%3}, {%4,%5,%6,%7}, {%8,%9}, {%0,%1,%2,%3};"
                 : "+f"(d[0]), "+f"(d[1]), "+f"(d[2]), "+f"(d[3])
                 : "r"(a[0]), "r"(a[1]), "r"(a[2]), "r"(a[3]), "r"(b[0]), "r"(b[1]));
}
__device__ __forceinline__ uint32_t mapa_u32(uint32_t a, uint32_t rank) {
    uint32_t d;
    asm("mapa.shared::cluster.u32 %0, %1, %2;" : "=r"(d) : "r"(a), "r"(rank));
    return d;
}
__device__ __forceinline__ void stsc32(uint32_t a, uint32_t v) {
    asm volatile("st.shared::cluster.u32 [%0], %1;" :: "r"(a), "r"(v) : "memory");
}
#define CLUSTER_ARRIVE() asm volatile("barrier.cluster.arrive.aligned;" ::: "memory")
#define CLUSTER_WAIT()   asm volatile("barrier.cluster.wait.aligned;"   ::: "memory")

__device__ __forceinline__ float sigm(float a)  {
    return __fdividef(1.0f, 1.0f + __expf(-a));
}
__device__ __forceinline__ float tanh_(float a) {
    return 1.0f - __fdividef(2.0f, 1.0f + __expf(2.0f * a));
}
__device__ __forceinline__ uint32_t h2u(__half2 h) { return *reinterpret_cast<uint32_t*>(&h); }

// K=256 pass, M=32 rows per warp (mt=2 tiles of 16) — used by xproj (M=128, warps 4wm x 2wn)
__device__ __forceinline__ void gemm2(uint32_t sAb, uint32_t sWb, int wm, int wn, int lane,
                                      float acc[2][3][2][4]) {
    const int l16 = lane & 15, h16 = (lane >> 4) & 1;
    const uint32_t aBase = sAb + (32 * wm + l16) * AROW + h16 * 16;
    const uint32_t bBase = sWb + (wn * 16 + l16) * AROW + h16 * 16;
#pragma unroll 4
    for (int kc = 0; kc < 16; kc++) {
        uint32_t a[2][4];
        ldsm4(a[0], aBase + kc * 32);
        ldsm4(a[1], aBase + 16 * AROW + kc * 32);
#pragma unroll
        for (int g = 0; g < 3; g++) {
            uint32_t b[4];
            ldsm4(b, bBase + g * 32 * AROW + kc * 32);
            uint32_t bj0[2] = {b[0], b[2]}, bj1[2] = {b[1], b[3]};
#pragma unroll
            for (int mt = 0; mt < 2; mt++) {
                mma16816(acc[mt][g][0], a[mt], bj0);
                mma16816(acc[mt][g][1], a[mt], bj1);
            }
        }
    }
}

// ---------------- prep ----------------
__global__ void prep_kernel(const float* __restrict__ W_ih, const float* __restrict__ W_hh,
                            const float* __restrict__ b_ih, const float* __restrict__ b_hh) {
    int idx = blockIdx.x * 256 + threadIdx.x;
    if (idx < 2 * UGN * 96 * 256) {
        int k = idx & 255, rest = idx >> 8;
        int j = rest % 96, ug = (rest / 96) & 7, m = rest / 768;
        int gate = j >> 5, u = j & 31;
        int orig = gate * 256 + ug * 32 + u;
        float wv = m ? W_hh[orig * 256 + k] : W_ih[orig * 256 + k];
        __half hi = __float2half_rn(wv);
        __half lo = __float2half_rn(wv - __half2float(hi));
        g_W[m][ug][0][j * 256 + k] = hi;
        g_W[m][ug][1][j * 256 + k] = lo;
    }
    if (idx < 256) {
        g_bias[idx]       = b_ih[idx]       + b_hh[idx];
        g_bias[256 + idx] = b_ih[256 + idx] + b_hh[256 + idx];
        g_bias[512 + idx] = b_ih[512 + idx];
        g_bias[768 + idx] = b_hh[512 + idx];
    }
}

// ---------------- phase A: xi = x @ W_hi^T, fp16 out, T-MAJOR ----------------
__global__ void __launch_bounds__(256, 1) xproj_kernel(const float* __restrict__ x) {
    extern __shared__ __align__(16) char sp[];
    const uint32_t sA = smem_u32(sp);
    const int tid = threadIdx.x, lane = tid & 31, w = tid >> 5;
    const int wm = w & 3, wn = w >> 2;
    const size_t bt0 = (size_t)blockIdx.x * 128;

    // x tile -> fp16 A (rows = 128 consecutive (b,t))
    const float4* x4 = (const float4*)(x + bt0 * 256);
    for (int i = tid; i < 8192; i += 256) {
        int row = i >> 6, c4 = i & 63;
        float4 v = __ldg(&x4[(size_t)row * 64 + c4]);
        uint2 hv = {h2u(__floats2half2_rn(v.x, v.y)), h2u(__floats2half2_rn(v.z, v.w))};
        *(uint2*)(sp + row * AROW + c4 * 8) = hv;
    }

#pragma unroll 1
    for (int ug = 0; ug < UGN; ug++) {
        float acc[2][3][2][4];
#pragma unroll
        for (int mt = 0; mt < 2; mt++)
#pragma unroll
            for (int g = 0; g < 3; g++)
#pragma unroll
                for (int j = 0; j < 2; j++)
#pragma unroll
                    for (int e = 0; e < 4; e++) acc[mt][g][j][e] = 0.0f;

        __syncthreads();  // A staged / previous gemm reads of W done
        for (int i = tid; i < 3072; i += 256) {
            int j = i >> 5, q = i & 31;
            *(uint4*)(sp + OFF_WX + j * AROW + q * 16) =
                ((const uint4*)&g_W[0][ug][0][0])[j * 32 + q];
        }
        __syncthreads();
        gemm2(sA, sA + OFF_WX, wm, wn, lane, acc);   // W_hi @ x

#pragma unroll
        for (int mt = 0; mt < 2; mt++)
#pragma unroll
            for (int eh = 0; eh < 2; eh++) {
                int rl = 32 * wm + 16 * mt + (lane >> 2) + 8 * eh;
                size_t bt = bt0 + rl;
                size_t bb = bt >> 9, tt = bt & 511;       // x is [b][t][I], T=512
                __half* go = g_xi + (tt * Bsz + bb) * 768 + ug * 96 + wn * 16 + 2 * (lane & 3);
#pragma unroll
                for (int g = 0; g < 3; g++)
#pragma unroll
                    for (int j = 0; j < 2; j++)
                        *(uint32_t*)(go + g * 32 + j * 8) =
                            h2u(__floats2half2_rn(acc[mt][g][j][eh * 2],
                                                  acc[mt][g][j][eh * 2 + 1]));
            }
    }
}

// ---------------- recurrence: 16 clusters x 8 CTAs, 512 threads (M=64, warp N=24) -------
// h exchange via DSMEM: each CTA writes its 32 h-columns into all 8 peers' A tiles
// (double buffered), one cluster barrier per step. No L2 flags, no global h buffer.
__global__ void __launch_bounds__(512, 1) __cluster_dims__(UGN, 1, 1)
gru_rec(const int* __restrict__ seqlen, float* __restrict__ out) {
    extern __shared__ __align__(16) char sp[];
    const uint32_t sA = smem_u32(sp);
    const int tid = threadIdx.x, lane = tid & 31, w = tid >> 5;
    const int wm = w & 3, wn = w >> 2;                 // wm: 16-row block, wn: 8-unit block
    const int l16 = lane & 15, h16 = (lane >> 4) & 1;
    const int bg = blockIdx.x >> 3, ug = blockIdx.x & 7;   // ug == cluster rank

    // W_hh hi resident all steps
    for (int i = tid; i < 3072; i += 512) {
        int j = i >> 5, q = i & 31;
        *(uint4*)(sp + OFF_W + j * AROW + q * 16) =
            ((const uint4*)&g_W[1][ug][0][0])[j * 32 + q];
    }
    // A0 = A1 = 0 (h0) — contiguous 67584 B = 4224 uint4
    {
        uint4 z = {0, 0, 0, 0};
        for (int i = tid; i < 4224; i += 512) ((uint4*)sp)[i] = z;
    }

    // thread-resident biases (2 units) and seqlen (2 rows)
    const int ucol = 8 * wn + 2 * (lane & 3);          // first of thread's 2 unit-cols
    float br[2], bz[2], bxn[2], bhg[2];
#pragma unroll
    for (int e1 = 0; e1 < 2; e1++) {
        int hu = ug * 32 + ucol + e1;
        br[e1] = g_bias[hu]; bz[e1] = g_bias[256 + hu];
        bxn[e1] = g_bias[512 + hu]; bhg[e1] = g_bias[768 + hu];
    }
    const int row0 = 16 * wm + (lane >> 2);
    int Lr[2];
    Lr[0] = seqlen[bg * 64 + row0];
    Lr[1] = seqlen[bg * 64 + row0 + 8];

    // peer SMEM base addresses (offset arithmetic stays valid within the window)
    uint32_t pb[UGN];
#pragma unroll
    for (int p = 0; p < UGN; p++) pb[p] = mapa_u32(sA, p);

    float hold[2][2], hn[2][2];
#pragma unroll
    for (int eh = 0; eh < 2; eh++)
#pragma unroll
        for (int e1 = 0; e1 < 2; e1++) { hold[eh][e1] = 0.0f; hn[eh][e1] = 0.0f; }

    __syncthreads();       // local init complete
    CLUSTER_ARRIVE();      // arrive #0: zeros + W visible after first wait

    const uint32_t aBase = sA + (16 * wm + l16) * AROW + h16 * 16;
    const uint32_t bRow  = (8 * wn + (lane & 7)) * AROW + ((l16 >> 3) & 1) * 16;
    // thread's h destination offsets within any CTA's A tile (both rows)
    const uint32_t hOff0 = (uint32_t)(row0 * AROW + (ug * 32 + ucol) * 2);
    const uint32_t hOff1 = hOff0 + 8 * AROW;

#pragma unroll 1
    for (int t = 0; t < Tsz; t++) {
        // xi preload (fp16, t-major: contiguous CTA block) — hides behind cluster wait
        float2 xif[2][3];
#pragma unroll
        for (int eh = 0; eh < 2; eh++) {
            const __half* xb = g_xi + ((size_t)t * Bsz + bg * 64 + row0 + 8 * eh) * 768 +
                               ug * 96 + ucol;
#pragma unroll
            for (int g = 0; g < 3; g++)
                xif[eh][g] = __half22float2(__ldg((const __half2*)(xb + g * 32)));
        }

        CLUSTER_WAIT();    // all peers' h_{t-1} writes into read-buffer are visible

        const uint32_t aB = aBase + ((t + 1) & 1) * OFF_A1;   // read buf[(t-1)&1]
        float acc[3][4];
#pragma unroll
        for (int g = 0; g < 3; g++)
#pragma unroll
            for (int e = 0; e < 4; e++) acc[g][e] = 0.0f;

        // single-pass GEMM: per kc, per gate: W_hi @ h
#pragma unroll 4
        for (int kc = 0; kc < 16; kc++) {
            uint32_t ah[4];
            ldsm4(ah, aB + kc * 32);
#pragma unroll
            for (int g = 0; g < 3; g++) {
                uint32_t bh[2];
                ldsm2(bh, sA + OFF_W + g * 32 * AROW + bRow + kc * 32);
                mma16816(acc[g], ah, bh);
            }
        }

        // epilogue: gates + h update (hold fp32); DSMEM-broadcast fp16 h to all 8 peers
        const uint32_t wOff = (uint32_t)((t & 1) * OFF_A1);
#pragma unroll
        for (int eh = 0; eh < 2; eh++) {
            float hv2[2];
#pragma unroll
            for (int e1 = 0; e1 < 2; e1++) {
                int e = 2 * eh + e1;
                float xr = e1 ? xif[eh][0].y : xif[eh][0].x;
                float xz = e1 ? xif[eh][1].y : xif[eh][1].x;
                float xn = e1 ? xif[eh][2].y : xif[eh][2].x;
                float rr = sigm(acc[0][e] + xr + br[e1]);
                float zz = sigm(acc[1][e] + xz + bz[e1]);
                float nn = tanh_(xn + bxn[e1] + rr * (acc[2][e] + bhg[e1]));
                float hv = zz * (hold[eh][e1] - nn) + nn;
                hold[eh][e1] = hv;
                if (t + 1 == Lr[eh]) hn[eh][e1] = hv;
                hv2[e1] = hv;
            }
            uint32_t val = h2u(__floats2half2_rn(hv2[0], hv2[1]));
            uint32_t off = wOff + (eh ? hOff1 : hOff0);
#pragma unroll
            for (int p = 0; p < UGN; p++) stsc32(pb[p] + off, val);
        }
        CLUSTER_ARRIVE();  // h_t published to every peer's write-buffer
    }
    CLUSTER_WAIT();        // no CTA exits while peers may still write into its SMEM

#pragma unroll
    for (int eh = 0; eh < 2; eh++)
#pragma unroll
        for (int e1 = 0; e1 < 2; e1++)
            out[(size_t)(bg * 64 + row0 + 8 * eh) * 256 + ug * 32 + ucol + e1] = hn[eh][e1];
}

extern "C" void kernel_launch(void* const* d_in, const int* in_sizes, int n_in,
                              void* d_out, int out_size) {
    const float* x      = (const float*)d_in[0];
    const int*   seqlen = (const int*)d_in[1];
    const float* W_ih   = (const float*)d_in[2];
    const float* W_hh   = (const float*)d_in[3];
    const float* b_ih   = (const float*)d_in[4];
    const float* b_hh   = (const float*)d_in[5];
    float*       out    = (float*)d_out;

    static bool init = false;
    if (!init) {
        cudaFuncSetAttribute(xproj_kernel, cudaFuncAttributeMaxDynamicSharedMemorySize, SMEM_XP);
        cudaFuncSetAttribute(gru_rec, cudaFuncAttributeMaxDynamicSharedMemorySize, SMEM_REC);
        init = true;
    }
    prep_kernel<<<1536, 256>>>(W_ih, W_hh, b_ih, b_hh);
    xproj_kernel<<<(Bsz * Tsz) / 128, 256, SMEM_XP>>>(x);
    gru_rec<<<MGN * UGN, 512, SMEM_REC>>>(seqlen, out);
}